// round 3
// baseline (speedup 1.0000x reference)
#include <cuda_runtime.h>
#include <cuda_bf16.h>

// Shapes (fixed): B=1, C=8, O=8, G=12, X=Y=Z=12, H=8, W=40, Bb=7 (basis), 27 taps
// x      : (1,8,12,12,12,8,40) f32   strides: c 552960, xi 46080, yi 3840, zi 320, h 40, w 1
// weight : (8,8,3,3,3,7)       f32   o 1512, c 189, f 7, b 1
// bias   : (8,3,3,3)           f32
// basis  : (12,7,3,3)          f32   g 63, b 9, u 3, v 1
// out    : (1,96,12,12,12,8,40) f32  go 552960, same spatial strides as x
//
// Factored algorithm (8.2x fewer FLOPs than the naive conv):
//   Y[b,o,h,w]   = sum_{c,f} x[c, n+f, h, w] * weight[o,c,f,b]          (per n)
//   out[g*8+o,.] = biasSum[o] + sum_{b,u,v} basis[geff,b,u,v] * Y[b,o,hh0+u,ww0+v]
// with hh0=clip(h,1,6)-1, ww0=clip(w,1,38)-1, geff=(g+border)%12
// (I/J/T/bias_basis inputs are deterministic clip/border maps; computed inline)

#define NT 320
#define SMEM_FLOATS (12096 + 756 + 8 + 7680 + 17920)
#define SMEM_BYTES (SMEM_FLOATS * 4)

__global__ __launch_bounds__(NT, 1)
void gconv_main(const float* __restrict__ x,
                const float* __restrict__ weight,
                const float* __restrict__ bias,
                const float* __restrict__ basis,
                float* __restrict__ out)
{
    extern __shared__ float smem[];
    float* sW      = smem;            // [216][56]  (c*27+f) x (o*7+b)
    float* sBasis  = sW + 12096;      // [12][63]
    float* sBiasS  = sBasis + 756;    // [8]
    float* sX      = sBiasS + 8;      // [8][960]   c x (fk*320 + h*40+w)
    float* sY      = sX + 7680;       // [56][320]  (o*7+b) x pix

    const int tid = threadIdx.x;
    const int n   = blockIdx.x;           // 0..728
    const int xi  = n / 81;
    const int yi  = (n / 9) % 9;
    const int zi  = n % 9;

    // ---- load weight reorganized: sW[(c*27+f)*56 + o*7 + b] ----
    for (int idx = tid; idx < 12096; idx += NT) {
        int o  = idx / 1512;
        int r  = idx % 1512;
        int c  = r / 189;
        int r2 = r % 189;          // f*7 + b
        int f  = r2 / 7;
        int b  = r2 % 7;
        sW[(c * 27 + f) * 56 + o * 7 + b] = weight[idx];
    }
    for (int idx = tid; idx < 756; idx += NT) sBasis[idx] = basis[idx];
    if (tid < 8) {
        float s = 0.f;
        #pragma unroll
        for (int t = 0; t < 27; t++) s += bias[tid * 27 + t];
        sBiasS[tid] = s;
    }

    // ---- Phase 1: Y[o*7+b][pix] ----
    const int t_o = tid / 40;   // 0..7 : o
    const int t_p = tid % 40;   // 0..39: w column; pixels t_p + 40*j, j=0..7

    float acc[7][8];
    #pragma unroll
    for (int i = 0; i < 7; i++)
        #pragma unroll
        for (int j = 0; j < 8; j++) acc[i][j] = 0.f;

    const float* xn = x + (size_t)xi * 46080 + (size_t)yi * 3840 + (size_t)zi * 320;

    for (int ff = 0; ff < 9; ff++) {
        const int fi = ff / 3, fj = ff % 3;
        __syncthreads();
        // stage x[c=0..7, xi+fi, yi+fj, zi..zi+2, :, :]: 8 rows of 960 floats
        // = 1920 float4 = 6 per thread
        const float* xb = xn + fi * 46080 + fj * 3840;
        #pragma unroll
        for (int r = 0; r < 6; r++) {
            int e4 = tid + r * 320;        // 0..1919
            int c  = e4 / 240;             // 240 float4 per c-row
            int p4 = e4 % 240;
            float4 v = *reinterpret_cast<const float4*>(xb + (size_t)c * 552960 + p4 * 4);
            *reinterpret_cast<float4*>(sX + c * 960 + p4 * 4) = v;
        }
        __syncthreads();
        #pragma unroll
        for (int fk = 0; fk < 3; fk++) {
            const int f = fi * 9 + fj * 3 + fk;
            #pragma unroll
            for (int c = 0; c < 8; c++) {
                float xr[8];
                #pragma unroll
                for (int j = 0; j < 8; j++) xr[j] = sX[c * 960 + fk * 320 + t_p + 40 * j];
                const float* wp = sW + (c * 27 + f) * 56 + t_o * 7;
                float wr[7];
                #pragma unroll
                for (int i = 0; i < 7; i++) wr[i] = wp[i];
                #pragma unroll
                for (int i = 0; i < 7; i++)
                    #pragma unroll
                    for (int j = 0; j < 8; j++)
                        acc[i][j] = fmaf(wr[i], xr[j], acc[i][j]);
            }
        }
    }
    __syncthreads();
    #pragma unroll
    for (int i = 0; i < 7; i++)
        #pragma unroll
        for (int j = 0; j < 8; j++)
            sY[(t_o * 7 + i) * 320 + t_p + 40 * j] = acc[i][j];
    __syncthreads();

    // ---- Phase 2: per-pixel 12x8 output block ----
    const int h = tid / 40, w = tid % 40;
    const int hh0 = min(max(h, 1), 6) - 1;
    const int ww0 = min(max(w, 1), 38) - 1;
    const int bshift = ((h == 0) | (h == 7) | (w == 0) | (w == 39)) ? 1 : 0;

    int gbase[12];
    #pragma unroll
    for (int g = 0; g < 12; g++) {
        int ge = g + bshift;
        if (ge >= 12) ge -= 12;
        gbase[g] = ge * 63;
    }

    float accP[12][8];
    #pragma unroll
    for (int g = 0; g < 12; g++)
        #pragma unroll
        for (int o = 0; o < 8; o++) accP[g][o] = sBiasS[o];

    #pragma unroll
    for (int b = 0; b < 7; b++) {
        #pragma unroll
        for (int u = 0; u < 3; u++) {
            #pragma unroll
            for (int v = 0; v < 3; v++) {
                const int kk = b * 9 + u * 3 + v;
                const int yoff = (hh0 + u) * 40 + (ww0 + v);
                float yv[8];
                #pragma unroll
                for (int o = 0; o < 8; o++)
                    yv[o] = sY[(o * 7 + b) * 320 + yoff];
                #pragma unroll
                for (int g = 0; g < 12; g++) {
                    const float bs = sBasis[gbase[g] + kk];
                    #pragma unroll
                    for (int o = 0; o < 8; o++)
                        accP[g][o] = fmaf(bs, yv[o], accP[g][o]);
                }
            }
        }
    }

    // ---- store interior: out[go, xi+1, yi+1, zi+1, h, w] ----
    float* ob = out + (size_t)(xi + 1) * 46080 + (size_t)(yi + 1) * 3840
                    + (size_t)(zi + 1) * 320 + h * 40 + w;
    #pragma unroll
    for (int g = 0; g < 12; g++)
        #pragma unroll
        for (int o = 0; o < 8; o++)
            ob[(size_t)(g * 8 + o) * 552960] = accP[g][o];
}

// Zero only the non-interior shell cells. One block = one (go, X, Y, Z) cell
// = 320 floats = 80 float4.
__global__ void zero_shell(float* __restrict__ out)
{
    const int e    = blockIdx.x;        // 0 .. 96*1728-1
    const int go   = e / 1728;
    const int cell = e % 1728;
    const int cx = cell / 144, cy = (cell / 12) % 12, cz = cell % 12;
    if (cx >= 1 && cx <= 9 && cy >= 1 && cy <= 9 && cz >= 1 && cz <= 9) return;
    float4* p = reinterpret_cast<float4*>(out + (size_t)go * 552960 + (size_t)cell * 320);
    p[threadIdx.x] = make_float4(0.f, 0.f, 0.f, 0.f);
}

extern "C" void kernel_launch(void* const* d_in, const int* in_sizes, int n_in,
                              void* d_out, int out_size)
{
    const float* x      = (const float*)d_in[0];
    const float* weight = (const float*)d_in[1];
    const float* bias   = (const float*)d_in[2];
    const float* basis  = (const float*)d_in[3];
    // d_in[4..7] = I, J, T, bias_basis: deterministic clip/border maps, computed inline.
    float* out = (float*)d_out;

    cudaFuncSetAttribute(gconv_main, cudaFuncAttributeMaxDynamicSharedMemorySize, SMEM_BYTES);

    zero_shell<<<96 * 1728, 80>>>(out);
    gconv_main<<<729, NT, SMEM_BYTES>>>(x, weight, bias, basis, out);
}

// round 4
// speedup vs baseline: 1.8380x; 1.8380x over previous
#include <cuda_runtime.h>
#include <cuda_bf16.h>

// Shapes (fixed): B=1, C=8, O=8, G=12, X=Y=Z=12, H=8, W=40, Bb=7 (basis), 27 taps
// x      : (1,8,12,12,12,8,40) f32   strides: c 552960, xi 46080, yi 3840, zi 320, h 40, w 1
// weight : (8,8,3,3,3,7)       f32   o 1512, c 189, f 7, b 1
// bias   : (8,3,3,3)           f32
// basis  : (12,7,3,3)          f32   g 63, b 9, u 3, v 1
// out    : (1,96,12,12,12,8,40) f32  go 552960, same spatial strides as x
//
// Factored algorithm (8.2x fewer FLOPs than the naive conv):
//   Y[b,o,h,w]   = sum_{c,f} x[c, n+f, h, w] * weight[o,c,f,b]          (per n)
//   out[g*8+o,.] = biasSum[o] + sum_{b,u,v} basis[geff,b,u,v] * Y[b,o,hh0+u,ww0+v]
// with hh0=clip(h,1,6)-1, ww0=clip(w,1,38)-1, geff=(g+border)%12

#define NT 640
// smem: sW[216*64] + sBasis[756] + sBiasS[8(+4 pad)] + sX[8*960] + sY[56*320]
#define SMEM_FLOATS (13824 + 756 + 12 + 7680 + 17920)
#define SMEM_BYTES (SMEM_FLOATS * 4)

__device__ float gW[13824];     // [(c*27+f)][o*8+b], b==7 lane zero-padded
__device__ float gBiasS[8];

// One-shot prep: reorganize weight + bias sums (tiny, runs once per replay).
__global__ void prep_kernel(const float* __restrict__ weight,
                            const float* __restrict__ bias)
{
    int idx = blockIdx.x * 256 + threadIdx.x;
    if (idx < 13824) {
        int row = idx >> 6;          // c*27+f
        int col = idx & 63;          // o*8+b
        int b = col & 7, o = col >> 3;
        int c = row / 27, f = row % 27;
        gW[idx] = (b < 7) ? weight[o * 1512 + c * 189 + f * 7 + b] : 0.f;
    }
    if (idx < 8) {
        float s = 0.f;
        #pragma unroll
        for (int t = 0; t < 27; t++) s += bias[idx * 27 + t];
        gBiasS[idx] = s;
    }
}

__global__ __launch_bounds__(NT, 1)
void gconv_main(const float* __restrict__ x,
                const float* __restrict__ basis,
                float* __restrict__ out)
{
    extern __shared__ float smem[];
    float* sW      = smem;            // [216][64]
    float* sBasis  = sW + 13824;      // [12][63]
    float* sBiasS  = sBasis + 756;    // [8] (+4 pad)
    float* sX      = sBiasS + 12;     // [8][960]   c x (fk*320 + pix)
    float* sY      = sX + 7680;       // [56][320]  (o*7+b) x pix

    const int tid = threadIdx.x;
    const int n   = blockIdx.x;           // 0..728
    const int xi  = n / 81;
    const int yi  = (n / 9) % 9;
    const int zi  = n % 9;

    // ---- stage constants (linear, vectorized) ----
    {
        float4* sW4 = reinterpret_cast<float4*>(sW);
        const float4* gW4 = reinterpret_cast<const float4*>(gW);
        for (int i = tid; i < 13824 / 4; i += NT) sW4[i] = gW4[i];
        for (int i = tid; i < 756; i += NT) sBasis[i] = basis[i];
        if (tid < 8) sBiasS[tid] = gBiasS[tid];
    }

    // ---- Phase 1: Y[o*7+b][pix] ----
    // thread = (t_o, t_q): o = tid/80, 4 consecutive pixels 4*t_q..4*t_q+3
    const int t_o = tid / 80;
    const int t_q = tid % 80;

    float acc[7][4];
    #pragma unroll
    for (int i = 0; i < 7; i++)
        #pragma unroll
        for (int j = 0; j < 4; j++) acc[i][j] = 0.f;

    const float* xn = x + (size_t)xi * 46080 + (size_t)yi * 3840 + (size_t)zi * 320;

    for (int ff = 0; ff < 9; ff++) {
        const int fi = ff / 3, fj = ff % 3;
        __syncthreads();
        // stage x[c=0..7, xi+fi, yi+fj, zi..zi+2, :, :]: 8 rows x 960 floats
        // = 1920 float4, 3 per thread
        const float4* xb4 = reinterpret_cast<const float4*>(xn + fi * 46080 + fj * 3840);
        float4* sX4 = reinterpret_cast<float4*>(sX);
        #pragma unroll
        for (int r = 0; r < 3; r++) {
            int e4 = tid + r * NT;         // 0..1919
            int c  = e4 / 240;
            int p4 = e4 % 240;
            sX4[c * 240 + p4] = xb4[(size_t)c * 138240 + p4];
        }
        __syncthreads();
        #pragma unroll
        for (int fk = 0; fk < 3; fk++) {
            #pragma unroll
            for (int c = 0; c < 8; c++) {
                const int f = fi * 9 + fj * 3 + fk;
                float4 xv = *reinterpret_cast<const float4*>(sX + c * 960 + fk * 320 + t_q * 4);
                const float* wp = sW + (c * 27 + f) * 64 + t_o * 8;
                float4 w0 = *reinterpret_cast<const float4*>(wp);
                float4 w1 = *reinterpret_cast<const float4*>(wp + 4);
                float wr[7] = {w0.x, w0.y, w0.z, w0.w, w1.x, w1.y, w1.z};
                float xr[4] = {xv.x, xv.y, xv.z, xv.w};
                #pragma unroll
                for (int i = 0; i < 7; i++)
                    #pragma unroll
                    for (int j = 0; j < 4; j++)
                        acc[i][j] = fmaf(wr[i], xr[j], acc[i][j]);
            }
        }
    }
    __syncthreads();
    #pragma unroll
    for (int i = 0; i < 7; i++) {
        float4 v = make_float4(acc[i][0], acc[i][1], acc[i][2], acc[i][3]);
        *reinterpret_cast<float4*>(sY + (t_o * 7 + i) * 320 + t_q * 4) = v;
    }
    __syncthreads();

    // ---- Phase 2: thread = (ghalf, pixel); each computes 6 g x 8 o ----
    const int ghalf = tid / 320;          // 0 or 1 -> g in [6*ghalf, 6*ghalf+6)
    const int pix   = tid % 320;
    const int h = pix / 40, w = pix % 40;
    const int hh0 = min(max(h, 1), 6) - 1;
    const int ww0 = min(max(w, 1), 38) - 1;
    const int bshift = ((h == 0) | (h == 7) | (w == 0) | (w == 39)) ? 1 : 0;

    int gbase[6];
    #pragma unroll
    for (int g = 0; g < 6; g++) {
        int ge = g + 6 * ghalf + bshift;
        if (ge >= 12) ge -= 12;
        gbase[g] = ge * 63;
    }

    float accP[6][8];
    #pragma unroll
    for (int g = 0; g < 6; g++)
        #pragma unroll
        for (int o = 0; o < 8; o++) accP[g][o] = sBiasS[o];

    #pragma unroll
    for (int b = 0; b < 7; b++) {
        #pragma unroll
        for (int u = 0; u < 3; u++) {
            #pragma unroll
            for (int v = 0; v < 3; v++) {
                const int kk = b * 9 + u * 3 + v;
                const int yoff = (hh0 + u) * 40 + (ww0 + v);
                float yv[8];
                #pragma unroll
                for (int o = 0; o < 8; o++)
                    yv[o] = sY[(o * 7 + b) * 320 + yoff];
                #pragma unroll
                for (int g = 0; g < 6; g++) {
                    const float bs = sBasis[gbase[g] + kk];
                    #pragma unroll
                    for (int o = 0; o < 8; o++)
                        accP[g][o] = fmaf(bs, yv[o], accP[g][o]);
                }
            }
        }
    }

    // ---- store interior: out[(6*ghalf+g)*8+o, xi+1, yi+1, zi+1, h, w] ----
    float* ob = out + (size_t)(xi + 1) * 46080 + (size_t)(yi + 1) * 3840
                    + (size_t)(zi + 1) * 320 + h * 40 + w
                    + (size_t)ghalf * 6 * 8 * 552960;
    #pragma unroll
    for (int g = 0; g < 6; g++)
        #pragma unroll
        for (int o = 0; o < 8; o++)
            ob[(size_t)(g * 8 + o) * 552960] = accP[g][o];
}

// Zero the non-interior shell. One thread = one float4 slot; interior skipped.
// Total slots: 96 * 1728 * 80 = 13,271,040 -> grid 25920 x 512.
__global__ __launch_bounds__(512)
void zero_shell(float* __restrict__ out)
{
    const int idx   = blockIdx.x * 512 + threadIdx.x;
    const int cellE = idx / 80;
    const int s     = idx % 80;
    const int go    = cellE / 1728;
    const int cell  = cellE % 1728;
    const int cx = cell / 144, cy = (cell / 12) % 12, cz = cell % 12;
    if (cx >= 1 && cx <= 9 && cy >= 1 && cy <= 9 && cz >= 1 && cz <= 9) return;
    reinterpret_cast<float4*>(out + (size_t)go * 552960 + (size_t)cell * 320)[s] =
        make_float4(0.f, 0.f, 0.f, 0.f);
}

extern "C" void kernel_launch(void* const* d_in, const int* in_sizes, int n_in,
                              void* d_out, int out_size)
{
    const float* x      = (const float*)d_in[0];
    const float* weight = (const float*)d_in[1];
    const float* bias   = (const float*)d_in[2];
    const float* basis  = (const float*)d_in[3];
    // d_in[4..7] = I, J, T, bias_basis: deterministic clip/border maps, computed inline.
    float* out = (float*)d_out;

    cudaFuncSetAttribute(gconv_main, cudaFuncAttributeMaxDynamicSharedMemorySize, SMEM_BYTES);

    prep_kernel<<<54, 256>>>(weight, bias);
    zero_shell<<<25920, 512>>>(out);
    gconv_main<<<729, NT, SMEM_BYTES>>>(x, basis, out);
}